// round 10
// baseline (speedup 1.0000x reference)
#include <cuda_runtime.h>
#include <cuda_fp16.h>
#include <math.h>
#include <stdint.h>

#define Bsz   4096
#define Nn    32
#define Hh    8
#define Dd    64
#define HIDd  512
#define MROWS (Bsz * Nn)
#define QKV_COLS (3 * HIDd)
#define Kdim  512

static const size_t OUT_ELEMS  = (size_t)MROWS * HIDd;
static const size_t ATTN_ELEMS = (size_t)Bsz * Hh * Nn * Nn;

__device__ float g_qkv[(size_t)MROWS * QKV_COLS];
__device__ __half g_Ahi[(size_t)MROWS * HIDd];
__device__ __half g_Whi[1048576 + 16];
__device__ float g_attn_fb[(size_t)Bsz * Hh * Nn * Nn];
__device__ unsigned int g_mask_bits[32];

#define WQKV_ELE (QKV_COLS * HIDd)

// ---------------- PTX helpers ----------------
__device__ __forceinline__ uint32_t smem_u32(const void* p) {
    uint32_t a;
    asm("{ .reg .u64 t; cvta.to.shared.u64 t, %1; cvt.u32.u64 %0, t; }"
        : "=r"(a) : "l"(p));
    return a;
}
__device__ __forceinline__ void cp16(uint32_t dst, const void* src) {
    asm volatile("cp.async.cg.shared.global [%0], [%1], 16;"
                 :: "r"(dst), "l"(src) : "memory");
}
#define CP_COMMIT() asm volatile("cp.async.commit_group;" ::: "memory")
#define CP_WAIT1()  asm volatile("cp.async.wait_group 1;" ::: "memory")
#define CP_WAIT0()  asm volatile("cp.async.wait_group 0;" ::: "memory")

#define LDSM4(r0, r1, r2, r3, addr) \
    asm volatile("ldmatrix.sync.aligned.m8n8.x4.shared.b16 {%0,%1,%2,%3}, [%4];" \
        : "=r"(r0), "=r"(r1), "=r"(r2), "=r"(r3) : "r"(addr))

#define MMA16816(c, a, b0, b1) \
    asm volatile("mma.sync.aligned.m16n8k16.row.col.f32.f16.f16.f32 " \
        "{%0,%1,%2,%3}, {%4,%5,%6,%7}, {%8,%9}, {%0,%1,%2,%3};" \
        : "+f"((c)[0]), "+f"((c)[1]), "+f"((c)[2]), "+f"((c)[3]) \
        : "r"((a)[0]), "r"((a)[1]), "r"((a)[2]), "r"((a)[3]), \
          "r"(b0), "r"(b1))

// ---------------- mask decode ----------------
__global__ void decode_mask_kernel(const unsigned char* __restrict__ raw) {
    __shared__ int onebyte;
    if (threadIdx.x == 0) {
        int ok = 1;
        for (int i = 0; i < 32; ++i) if (raw[33 * i] == 0) ok = 0;
        onebyte = ok;
    }
    __syncthreads();
    int i = threadIdx.x;
    unsigned int bits = 0;
    if (onebyte) {
        for (int j = 0; j < 32; ++j)
            if (raw[i * 32 + j] != 0) bits |= (1u << j);
    } else {
        const unsigned int* w = (const unsigned int*)raw;
        for (int j = 0; j < 32; ++j)
            if (w[i * 32 + j] != 0) bits |= (1u << j);
    }
    g_mask_bits[i] = bits;
}

// ---------------- fp32 -> fp16 convert ----------------
__global__ void __launch_bounds__(256)
split_hi_kernel(const float* __restrict__ in, __half* __restrict__ hi, int n4)
{
    int i = blockIdx.x * 256 + threadIdx.x;
    if (i >= n4) return;
    float4 x = ((const float4*)in)[i];
    __half2 h0; h0.x = __float2half_rn(x.x); h0.y = __float2half_rn(x.y);
    __half2 h1; h1.x = __float2half_rn(x.z); h1.y = __float2half_rn(x.w);
    ((__half2*)hi)[2 * i + 0] = h0;
    ((__half2*)hi)[2 * i + 1] = h1;
}

// ---------------- mma.sync fp16 GEMM (NT) ----------------
// C[m,n] = sum_k A[m,k]*B[n,k] + bias[n].
// CTA 128x256, 8 warps (warp tile 64x64, 2Mx4N grid), KC=32, 2-stage cp.async.
#define GM  128
#define GN  256
#define GKC 32
#define NCHUNK (Kdim / GKC)        // 16
#define APITCH 80                  // 32 fp16 + 16B pad per smem row
#define A_BYTES (128 * APITCH)     // 10240
#define B_BYTES (256 * APITCH)     // 20480
#define STAGE_BYTES (A_BYTES + B_BYTES)  // 30720
#define GEMM_SMEM (2 * STAGE_BYTES)      // 61440

__global__ void __launch_bounds__(256, 1)
gemm_tc(const __half* __restrict__ Ahi, const __half* __restrict__ Bhi,
        const float* __restrict__ bias, float* __restrict__ C, int Nc)
{
    extern __shared__ char smem[];
    const uint32_t sb = smem_u32(smem);
    const int t = threadIdx.x, wid = t >> 5, lane = t & 31;
    const int bm = blockIdx.y * GM, bn = blockIdx.x * GN;
    const int wm = (wid & 1) * 64;     // warp M offset (2 tiles)
    const int wn = (wid >> 1) * 64;    // warp N offset (4 tiles)

    float acc[4][8][4];
#pragma unroll
    for (int i = 0; i < 4; ++i)
#pragma unroll
        for (int j = 0; j < 8; ++j)
#pragma unroll
            for (int q = 0; q < 4; ++q) acc[i][j][q] = 0.0f;

    // Load a stage: A 128 rows + B 256 rows, 4x16B segments per row.
    // 1536 segments / 256 threads = 6 per thread.
    auto load_stage = [&](int st, int k0) {
        uint32_t base = sb + st * (uint32_t)STAGE_BYTES;
#pragma unroll
        for (int it = 0; it < 6; ++it) {
            int idx = t + 256 * it;        // 0..1535
            int r = idx >> 2, seg = idx & 3;
            if (r < 128) {
                uint32_t doff = (uint32_t)(r * APITCH + seg * 16);
                size_t so = (size_t)(bm + r) * Kdim + k0 + seg * 8;
                cp16(base + doff, Ahi + so);
            } else {
                int rb = r - 128;
                uint32_t doff = (uint32_t)(rb * APITCH + seg * 16);
                size_t so = (size_t)(bn + rb) * Kdim + k0 + seg * 8;
                cp16(base + A_BYTES + doff, Bhi + so);
            }
        }
        CP_COMMIT();
    };

    load_stage(0, 0);

    const uint32_t lrow  = lane & 15;
    const uint32_t lcolb = (lane >> 4) * 16;

    for (int c = 0; c < NCHUNK; ++c) {
        if (c + 1 < NCHUNK) {
            load_stage((c + 1) & 1, (c + 1) * GKC);
            CP_WAIT1();
        } else {
            CP_WAIT0();
        }
        __syncthreads();

        uint32_t base = sb + (uint32_t)(c & 1) * STAGE_BYTES;
#pragma unroll
        for (int s = 0; s < 2; ++s) {
            uint32_t colb = s * 32 + lcolb;
            uint32_t Ah[4][4];
#pragma unroll
            for (int mi = 0; mi < 4; ++mi) {
                uint32_t ad = base + (wm + mi * 16 + lrow) * APITCH + colb;
                LDSM4(Ah[mi][0], Ah[mi][1], Ah[mi][2], Ah[mi][3], ad);
            }
#pragma unroll
            for (int ni = 0; ni < 4; ++ni) {
                uint32_t bd = base + A_BYTES
                            + (wn + ni * 16 + lrow) * APITCH + colb;
                uint32_t h0, h1, h2, h3;
                LDSM4(h0, h1, h2, h3, bd);
#pragma unroll
                for (int mi = 0; mi < 4; ++mi) {
                    MMA16816(acc[mi][2 * ni],     Ah[mi], h0, h2);
                    MMA16816(acc[mi][2 * ni + 1], Ah[mi], h1, h3);
                }
            }
        }
        __syncthreads();
    }

    // Epilogue
    const int row0 = bm + wm + (lane >> 2);
    const int col0 = bn + wn + (lane & 3) * 2;
#pragma unroll
    for (int mi = 0; mi < 4; ++mi) {
#pragma unroll
        for (int nj = 0; nj < 8; ++nj) {
            int r = row0 + mi * 16;
            int cc = col0 + nj * 8;
            float b0 = __ldg(&bias[cc]), b1 = __ldg(&bias[cc + 1]);
            float* p0 = C + (size_t)r * Nc + cc;
            float* p1 = C + (size_t)(r + 8) * Nc + cc;
            p0[0] = acc[mi][nj][0] + b0;
            p0[1] = acc[mi][nj][1] + b1;
            p1[0] = acc[mi][nj][2] + b0;
            p1[1] = acc[mi][nj][3] + b1;
        }
    }
}

// ---------------- attention (fused ctx -> fp16) ----------------
__global__ void __launch_bounds__(128)
attn_kernel2(const float* __restrict__ qkv, __half* __restrict__ chi,
             float* __restrict__ attn_out)
{
    __shared__ float Qs[32][64];
    __shared__ float Ks[32][65];
    __shared__ float Vs[32][64];
    __shared__ float Ps[32][33];

    const int bh = blockIdx.x;
    const int b  = bh >> 3;
    const int h  = bh & 7;
    const int t  = threadIdx.x;
    const int wid = t >> 5, lane = t & 31;

    const float* base = qkv + (size_t)b * Nn * QKV_COLS + h * Dd;
#pragma unroll
    for (int r = 0; r < 4; ++r) {
        int idx = t + 128 * r;
        int i = idx >> 4, d4 = (idx & 15) * 4;
        size_t ro = (size_t)i * QKV_COLS + d4;
        float4 q = *(const float4*)&base[ro];
        float4 k = *(const float4*)&base[ro + HIDd];
        float4 v = *(const float4*)&base[ro + 2 * HIDd];
        *(float4*)&Qs[i][d4] = q;
        Ks[i][d4 + 0] = k.x; Ks[i][d4 + 1] = k.y;
        Ks[i][d4 + 2] = k.z; Ks[i][d4 + 3] = k.w;
        *(float4*)&Vs[i][d4] = v;
    }
    __syncthreads();

    {   // scores: warp wid owns rows [8w,8w+8), lane = column j
        const int j = lane;
        float a8[8];
#pragma unroll
        for (int r = 0; r < 8; ++r) a8[r] = 0.0f;
#pragma unroll 4
        for (int d = 0; d < 64; ++d) {
            float kv = Ks[j][d];
#pragma unroll
            for (int r = 0; r < 8; ++r)
                a8[r] += Qs[wid * 8 + r][d] * kv;
        }
        size_t abase = (size_t)bh * 1024;
#pragma unroll
        for (int r = 0; r < 8; ++r) {
            int i = wid * 8 + r;
            float s = ((g_mask_bits[i] >> j) & 1u) ? a8[r] * 0.125f : -1e9f;
            float mx = s;
#pragma unroll
            for (int o = 16; o; o >>= 1)
                mx = fmaxf(mx, __shfl_xor_sync(0xFFFFFFFFu, mx, o));
            float e = expf(s - mx);
            float sum = e;
#pragma unroll
            for (int o = 16; o; o >>= 1)
                sum += __shfl_xor_sync(0xFFFFFFFFu, sum, o);
            float pr = e / sum;
            Ps[i][j] = pr;
            attn_out[abase + (size_t)i * 32 + j] = pr;
        }
    }
    __syncthreads();

    {   // PV + fused fp16 conversion of ctx
        const int d  = t & 63;
        const int hh = t >> 6;
        float a2[16];
#pragma unroll
        for (int r = 0; r < 16; ++r) a2[r] = 0.0f;
#pragma unroll 4
        for (int j = 0; j < 32; ++j) {
            float v = Vs[j][d];
#pragma unroll
            for (int r = 0; r < 16; ++r)
                a2[r] += Ps[hh * 16 + r][j] * v;
        }
        size_t cb = (size_t)b * Nn * HIDd + h * Dd + d;
#pragma unroll
        for (int r = 0; r < 16; ++r)
            chi[cb + (size_t)(hh * 16 + r) * HIDd] = __float2half_rn(a2[r]);
    }
}

// ---------------- launch ----------------
extern "C" void kernel_launch(void* const* d_in, const int* in_sizes, int n_in,
                              void* d_out, int out_size) {
    const float*         X    = (const float*)d_in[0];
    const unsigned char* mask = (const unsigned char*)d_in[1];
    const float*         Wqkv = (const float*)d_in[2];
    const float*         bqkv = (const float*)d_in[3];
    const float*         Wo   = (const float*)d_in[4];
    const float*         bo   = (const float*)d_in[5];

    float *qkv_p, *attn_fb_p;
    __half *ahi_p, *whi_p;
    cudaGetSymbolAddress((void**)&qkv_p, g_qkv);
    cudaGetSymbolAddress((void**)&attn_fb_p, g_attn_fb);
    cudaGetSymbolAddress((void**)&ahi_p, g_Ahi);
    cudaGetSymbolAddress((void**)&whi_p, g_Whi);

    float* out = (float*)d_out;
    float *out_p, *attn_p;
    long long osz = (long long)out_size;
    if (osz >= (long long)(OUT_ELEMS + ATTN_ELEMS)) {
        out_p = out; attn_p = out + OUT_ELEMS;
    } else if (osz >= (long long)OUT_ELEMS) {
        out_p = out; attn_p = attn_fb_p;
    } else {
        attn_p = out; out_p = qkv_p;
    }

    cudaFuncSetAttribute(gemm_tc, cudaFuncAttributeMaxDynamicSharedMemorySize,
                         GEMM_SMEM);

    decode_mask_kernel<<<1, 32>>>(mask);

    // converts: X, Wqkv, Wo -> fp16
    {
        int n4 = (MROWS * HIDd) / 4;
        split_hi_kernel<<<(n4 + 255) / 256, 256>>>(X, ahi_p, n4);
        int w4 = WQKV_ELE / 4;
        split_hi_kernel<<<(w4 + 255) / 256, 256>>>(Wqkv, whi_p, w4);
        int o4 = (HIDd * HIDd) / 4;
        split_hi_kernel<<<(o4 + 255) / 256, 256>>>(Wo, whi_p + WQKV_ELE, o4);
    }

    // qkv = X @ Wqkv^T + bqkv   [131072 x 1536]
    gemm_tc<<<dim3(QKV_COLS / GN, MROWS / GM), 256, GEMM_SMEM>>>(
        ahi_p, whi_p, bqkv, qkv_p, QKV_COLS);

    // attention (writes ctx fp16 into g_Ahi)
    attn_kernel2<<<Bsz * Hh, 128>>>(qkv_p, ahi_p, attn_p);

    // out = ctx @ Wo^T + bo     [131072 x 512]
    gemm_tc<<<dim3(HIDd / GN, MROWS / GM), 256, GEMM_SMEM>>>(
        ahi_p, whi_p + WQKV_ELE, bo, out_p, HIDd);
}

// round 12
// speedup vs baseline: 1.7752x; 1.7752x over previous
#include <cuda_runtime.h>
#include <cuda_fp16.h>
#include <math.h>
#include <stdint.h>

#define Bsz   4096
#define Nn    32
#define Hh    8
#define Dd    64
#define HIDd  512
#define MROWS (Bsz * Nn)
#define QKV_COLS (3 * HIDd)
#define Kdim  512

static const size_t OUT_ELEMS  = (size_t)MROWS * HIDd;
static const size_t ATTN_ELEMS = (size_t)Bsz * Hh * Nn * Nn;

__device__ float g_qkv[(size_t)MROWS * QKV_COLS];
__device__ __half g_Ahi[(size_t)MROWS * HIDd];
__device__ __half g_Whi[1048576 + 16];
__device__ float g_attn_fb[(size_t)Bsz * Hh * Nn * Nn];
__device__ unsigned int g_mask_bits[32];

#define WQKV_ELE (QKV_COLS * HIDd)

// ---------------- PTX helpers ----------------
__device__ __forceinline__ uint32_t smem_u32(const void* p) {
    uint32_t a;
    asm("{ .reg .u64 t; cvta.to.shared.u64 t, %1; cvt.u32.u64 %0, t; }"
        : "=r"(a) : "l"(p));
    return a;
}
__device__ __forceinline__ void cp16(uint32_t dst, const void* src) {
    asm volatile("cp.async.cg.shared.global [%0], [%1], 16;"
                 :: "r"(dst), "l"(src) : "memory");
}
#define CP_COMMIT() asm volatile("cp.async.commit_group;" ::: "memory")
#define CP_WAIT2()  asm volatile("cp.async.wait_group 2;" ::: "memory")
#define CP_WAIT1()  asm volatile("cp.async.wait_group 1;" ::: "memory")
#define CP_WAIT0()  asm volatile("cp.async.wait_group 0;" ::: "memory")

#define LDSM4(r0, r1, r2, r3, addr) \
    asm volatile("ldmatrix.sync.aligned.m8n8.x4.shared.b16 {%0,%1,%2,%3}, [%4];" \
        : "=r"(r0), "=r"(r1), "=r"(r2), "=r"(r3) : "r"(addr))

#define MMA16816(c, a, b0, b1) \
    asm volatile("mma.sync.aligned.m16n8k16.row.col.f32.f16.f16.f32 " \
        "{%0,%1,%2,%3}, {%4,%5,%6,%7}, {%8,%9}, {%0,%1,%2,%3};" \
        : "+f"((c)[0]), "+f"((c)[1]), "+f"((c)[2]), "+f"((c)[3]) \
        : "r"((a)[0]), "r"((a)[1]), "r"((a)[2]), "r"((a)[3]), \
          "r"(b0), "r"(b1))

// ---------------- mask decode ----------------
__global__ void decode_mask_kernel(const unsigned char* __restrict__ raw) {
    __shared__ int onebyte;
    if (threadIdx.x == 0) {
        int ok = 1;
        for (int i = 0; i < 32; ++i) if (raw[33 * i] == 0) ok = 0;
        onebyte = ok;
    }
    __syncthreads();
    int i = threadIdx.x;
    unsigned int bits = 0;
    if (onebyte) {
        for (int j = 0; j < 32; ++j)
            if (raw[i * 32 + j] != 0) bits |= (1u << j);
    } else {
        const unsigned int* w = (const unsigned int*)raw;
        for (int j = 0; j < 32; ++j)
            if (w[i * 32 + j] != 0) bits |= (1u << j);
    }
    g_mask_bits[i] = bits;
}

// ---------------- fp32 -> fp16 convert ----------------
__global__ void __launch_bounds__(256)
split_hi_kernel(const float* __restrict__ in, __half* __restrict__ hi, int n4)
{
    int i = blockIdx.x * 256 + threadIdx.x;
    if (i >= n4) return;
    float4 x = ((const float4*)in)[i];
    __half2 h0; h0.x = __float2half_rn(x.x); h0.y = __float2half_rn(x.y);
    __half2 h1; h1.x = __float2half_rn(x.z); h1.y = __float2half_rn(x.w);
    ((__half2*)hi)[2 * i + 0] = h0;
    ((__half2*)hi)[2 * i + 1] = h1;
}

// ---------------- mma.sync fp16 GEMM (NT), R9 tiles + 3-stage pipe ----------
// C[m,n] = sum_k A[m,k]*B[n,k] + bias[n].
// CTA 128x128, 8 warps (warp tile 32x64), KC=32, 3-stage cp.async.
#define GM  128
#define GN  128
#define GKC 32
#define NCHUNK (Kdim / GKC)       // 16
#define APITCH 80                 // 32 fp16 + 16B pad per smem row
#define MAT_BYTES (128 * APITCH)  // 10240
#define STAGE_BYTES (2 * MAT_BYTES)   // Ah|Bh = 20480
#define GEMM_SMEM (3 * STAGE_BYTES)   // 61440

__global__ void __launch_bounds__(256, 2)
gemm_tc(const __half* __restrict__ Ahi, const __half* __restrict__ Bhi,
        const float* __restrict__ bias, float* __restrict__ C, int Nc)
{
    extern __shared__ char smem[];
    const uint32_t sb = smem_u32(smem);
    const int t = threadIdx.x, wid = t >> 5, lane = t & 31;
    const int bm = blockIdx.y * GM, bn = blockIdx.x * GN;
    const int wm = (wid & 3) * 32;     // warp M offset
    const int wn = (wid >> 2) * 64;    // warp N offset

    float acc[2][8][4];
#pragma unroll
    for (int i = 0; i < 2; ++i)
#pragma unroll
        for (int j = 0; j < 8; ++j)
#pragma unroll
            for (int q = 0; q < 4; ++q) acc[i][j][q] = 0.0f;

    auto load_stage = [&](int st, int k0) {
        uint32_t base = sb + st * (uint32_t)STAGE_BYTES;
#pragma unroll
        for (int it = 0; it < 2; ++it) {
            int idx = t + 256 * it;        // 0..511
            int r = idx >> 2, seg = idx & 3;
            uint32_t doff = (uint32_t)(r * APITCH + seg * 16);
            size_t soA = (size_t)(bm + r) * Kdim + k0 + seg * 8;
            size_t soB = (size_t)(bn + r) * Kdim + k0 + seg * 8;
            cp16(base + doff,             Ahi + soA);
            cp16(base + MAT_BYTES + doff, Bhi + soB);
        }
        CP_COMMIT();
    };

    load_stage(0, 0);
    load_stage(1, GKC);

    const uint32_t lrow  = lane & 15;
    const uint32_t lcolb = (lane >> 4) * 16;

    for (int c = 0; c < NCHUNK; ++c) {
        if (c + 2 < NCHUNK) {
            load_stage((c + 2) % 3, (c + 2) * GKC);
            CP_WAIT2();
        } else if (c + 1 < NCHUNK) {
            CP_WAIT1();
        } else {
            CP_WAIT0();
        }
        __syncthreads();

        uint32_t base = sb + (uint32_t)(c % 3) * STAGE_BYTES;
#pragma unroll
        for (int s = 0; s < 2; ++s) {
            uint32_t colb = s * 32 + lcolb;
            uint32_t Ah[2][4];
#pragma unroll
            for (int mi = 0; mi < 2; ++mi) {
                uint32_t ad = base + (wm + mi * 16 + lrow) * APITCH + colb;
                LDSM4(Ah[mi][0], Ah[mi][1], Ah[mi][2], Ah[mi][3], ad);
            }
#pragma unroll
            for (int ni = 0; ni < 4; ++ni) {
                uint32_t bd = base + MAT_BYTES
                            + (wn + ni * 16 + lrow) * APITCH + colb;
                uint32_t h0, h1, h2, h3;
                LDSM4(h0, h1, h2, h3, bd);
#pragma unroll
                for (int mi = 0; mi < 2; ++mi) {
                    MMA16816(acc[mi][2 * ni],     Ah[mi], h0, h2);
                    MMA16816(acc[mi][2 * ni + 1], Ah[mi], h1, h3);
                }
            }
        }
        __syncthreads();
    }

    // Epilogue
    const int row0 = bm + wm + (lane >> 2);
    const int col0 = bn + wn + (lane & 3) * 2;
#pragma unroll
    for (int mi = 0; mi < 2; ++mi) {
#pragma unroll
        for (int nj = 0; nj < 8; ++nj) {
            int r = row0 + mi * 16;
            int cc = col0 + nj * 8;
            float b0 = __ldg(&bias[cc]), b1 = __ldg(&bias[cc + 1]);
            float* p0 = C + (size_t)r * Nc + cc;
            float* p1 = C + (size_t)(r + 8) * Nc + cc;
            p0[0] = acc[mi][nj][0] + b0;
            p0[1] = acc[mi][nj][1] + b1;
            p1[0] = acc[mi][nj][2] + b0;
            p1[1] = acc[mi][nj][3] + b1;
        }
    }
}

// ---------------- attention (float4 smem, fused ctx -> fp16) ----------------
__global__ void __launch_bounds__(128)
attn_kernel2(const float* __restrict__ qkv, __half* __restrict__ chi,
             float* __restrict__ attn_out)
{
    __shared__ float Qs[32][64];
    __shared__ float Ks[32][68];   // pitch 68: float4-aligned, phase-conflict-free
    __shared__ float Vs[32][64];
    __shared__ float Ps[32][36];   // pitch 36: float4-aligned

    const int bh = blockIdx.x;
    const int b  = bh >> 3;
    const int h  = bh & 7;
    const int t  = threadIdx.x;
    const int wid = t >> 5, lane = t & 31;

    const float* base = qkv + (size_t)b * Nn * QKV_COLS + h * Dd;
#pragma unroll
    for (int r = 0; r < 4; ++r) {
        int idx = t + 128 * r;
        int i = idx >> 4, d4 = (idx & 15) * 4;
        size_t ro = (size_t)i * QKV_COLS + d4;
        float4 q = *(const float4*)&base[ro];
        float4 k = *(const float4*)&base[ro + HIDd];
        float4 v = *(const float4*)&base[ro + 2 * HIDd];
        *(float4*)&Qs[i][d4] = q;
        *(float4*)&Ks[i][d4] = k;
        *(float4*)&Vs[i][d4] = v;
    }
    __syncthreads();

    {   // scores: warp wid owns rows [8w,8w+8), lane = column j. float4 dots.
        const int j = lane;
        float a8[8];
#pragma unroll
        for (int r = 0; r < 8; ++r) a8[r] = 0.0f;
#pragma unroll 4
        for (int d4 = 0; d4 < 16; ++d4) {
            float4 kv = *(const float4*)&Ks[j][4 * d4];
#pragma unroll
            for (int r = 0; r < 8; ++r) {
                float4 qv = *(const float4*)&Qs[wid * 8 + r][4 * d4];
                a8[r] += qv.x * kv.x + qv.y * kv.y + qv.z * kv.z + qv.w * kv.w;
            }
        }
        size_t abase = (size_t)bh * 1024;
#pragma unroll
        for (int r = 0; r < 8; ++r) {
            int i = wid * 8 + r;
            float s = ((g_mask_bits[i] >> j) & 1u) ? a8[r] * 0.125f : -1e9f;
            float mx = s;
#pragma unroll
            for (int o = 16; o; o >>= 1)
                mx = fmaxf(mx, __shfl_xor_sync(0xFFFFFFFFu, mx, o));
            float e = expf(s - mx);
            float sum = e;
#pragma unroll
            for (int o = 16; o; o >>= 1)
                sum += __shfl_xor_sync(0xFFFFFFFFu, sum, o);
            float pr = e / sum;
            Ps[i][j] = pr;
            attn_out[abase + (size_t)i * 32 + j] = pr;
        }
    }
    __syncthreads();

    {   // PV: thread -> (half hh, column d); float4 over j.
        const int d  = t & 63;
        const int hh = t >> 6;
        float a2[16];
#pragma unroll
        for (int r = 0; r < 16; ++r) a2[r] = 0.0f;
#pragma unroll 2
        for (int j4 = 0; j4 < 8; ++j4) {
            float v0 = Vs[4 * j4 + 0][d];
            float v1 = Vs[4 * j4 + 1][d];
            float v2 = Vs[4 * j4 + 2][d];
            float v3 = Vs[4 * j4 + 3][d];
#pragma unroll
            for (int r = 0; r < 16; ++r) {
                float4 p = *(const float4*)&Ps[hh * 16 + r][4 * j4];
                a2[r] += p.x * v0 + p.y * v1 + p.z * v2 + p.w * v3;
            }
        }
        size_t cb = (size_t)b * Nn * HIDd + h * Dd + d;
#pragma unroll
        for (int r = 0; r < 16; ++r)
            chi[cb + (size_t)(hh * 16 + r) * HIDd] = __float2half_rn(a2[r]);
    }
}

// ---------------- launch ----------------
extern "C" void kernel_launch(void* const* d_in, const int* in_sizes, int n_in,
                              void* d_out, int out_size) {
    const float*         X    = (const float*)d_in[0];
    const unsigned char* mask = (const unsigned char*)d_in[1];
    const float*         Wqkv = (const float*)d_in[2];
    const float*         bqkv = (const float*)d_in[3];
    const float*         Wo   = (const float*)d_in[4];
    const float*         bo   = (const float*)d_in[5];

    float *qkv_p, *attn_fb_p;
    __half *ahi_p, *whi_p;
    cudaGetSymbolAddress((void**)&qkv_p, g_qkv);
    cudaGetSymbolAddress((void**)&attn_fb_p, g_attn_fb);
    cudaGetSymbolAddress((void**)&ahi_p, g_Ahi);
    cudaGetSymbolAddress((void**)&whi_p, g_Whi);

    float* out = (float*)d_out;
    float *out_p, *attn_p;
    long long osz = (long long)out_size;
    if (osz >= (long long)(OUT_ELEMS + ATTN_ELEMS)) {
        out_p = out; attn_p = out + OUT_ELEMS;
    } else if (osz >= (long long)OUT_ELEMS) {
        out_p = out; attn_p = attn_fb_p;
    } else {
        attn_p = out; out_p = qkv_p;
    }

    cudaFuncSetAttribute(gemm_tc, cudaFuncAttributeMaxDynamicSharedMemorySize,
                         GEMM_SMEM);

    decode_mask_kernel<<<1, 32>>>(mask);

    // converts: X, Wqkv, Wo -> fp16
    {
        int n4 = (MROWS * HIDd) / 4;
        split_hi_kernel<<<(n4 + 255) / 256, 256>>>(X, ahi_p, n4);
        int w4 = WQKV_ELE / 4;
        split_hi_kernel<<<(w4 + 255) / 256, 256>>>(Wqkv, whi_p, w4);
        int o4 = (HIDd * HIDd) / 4;
        split_hi_kernel<<<(o4 + 255) / 256, 256>>>(Wo, whi_p + WQKV_ELE, o4);
    }

    // qkv = X @ Wqkv^T + bqkv   [131072 x 1536]
    gemm_tc<<<dim3(QKV_COLS / GN, MROWS / GM), 256, GEMM_SMEM>>>(
        ahi_p, whi_p, bqkv, qkv_p, QKV_COLS);

    // attention (writes ctx fp16 into g_Ahi)
    attn_kernel2<<<Bsz * Hh, 128>>>(qkv_p, ahi_p, attn_p);

    // out = ctx @ Wo^T + bo     [131072 x 512]
    gemm_tc<<<dim3(HIDd / GN, MROWS / GM), 256, GEMM_SMEM>>>(
        ahi_p, whi_p + WQKV_ELE, bo, out_p, HIDd);
}